// round 3
// baseline (speedup 1.0000x reference)
#include <cuda_runtime.h>

#define NN 50000
#define FIN 256
#define NH 64

// Scratch (allocation-free rule: __device__ globals)
__device__ float g_xw[NN * NH];   // x @ W1 for current view
__device__ float g_h[NN * NH];    // hidden accumulator for current view
__device__ float g_deg1[NN];      // weighted degree -> dinv1
__device__ float g_deg2[NN];      // count degree -> dinv2
__device__ float g_hw[NN];        // h @ W2 per node

__global__ void k_zero_out(float* out, int n) {
    int i = blockIdx.x * blockDim.x + threadIdx.x;
    if (i < n) out[i] = 0.f;
}

__global__ void k_init_view() {
    int i = blockIdx.x * blockDim.x + threadIdx.x;
    if (i < NN) { g_deg1[i] = 1.f; g_deg2[i] = 1.f; }  // self-loop weight 1
    if (i < NN * NH) g_h[i] = 0.f;
}

// xw = x @ W1   (50000x256 @ 256x64), 64-row tile per block, 4x4 register tile
__global__ void k_gemm(const float* __restrict__ x, const float* __restrict__ W) {
    __shared__ float xs[64][65];   // [k][row], padded
    __shared__ float ws[64][64];   // [k][col]
    int tid  = threadIdx.x;
    int row0 = blockIdx.x * 64;
    int tx = tid & 15;   // col group (4 cols)
    int ty = tid >> 4;   // row group (4 rows)
    float acc[4][4];
#pragma unroll
    for (int i = 0; i < 4; i++)
#pragma unroll
        for (int j = 0; j < 4; j++) acc[i][j] = 0.f;

    for (int kc = 0; kc < FIN; kc += 64) {
#pragma unroll
        for (int i = 0; i < 16; i++) {
            int idx = tid + i * 256;       // 0..4095
            int r = idx >> 6;              // 0..63
            int k = idx & 63;              // 0..63
            int gr = row0 + r;
            xs[k][r] = (gr < NN) ? x[gr * FIN + kc + k] : 0.f;
            // W tile: ws[k_row][col] = W[(kc + k_row) * NH + col]
            ws[r][k] = W[(kc + r) * NH + k];
        }
        __syncthreads();
#pragma unroll 16
        for (int k = 0; k < 64; k++) {
            float a0 = xs[k][ty * 4 + 0];
            float a1 = xs[k][ty * 4 + 1];
            float a2 = xs[k][ty * 4 + 2];
            float a3 = xs[k][ty * 4 + 3];
            float4 b = *(const float4*)&ws[k][tx * 4];
            acc[0][0] += a0 * b.x; acc[0][1] += a0 * b.y; acc[0][2] += a0 * b.z; acc[0][3] += a0 * b.w;
            acc[1][0] += a1 * b.x; acc[1][1] += a1 * b.y; acc[1][2] += a1 * b.z; acc[1][3] += a1 * b.w;
            acc[2][0] += a2 * b.x; acc[2][1] += a2 * b.y; acc[2][2] += a2 * b.z; acc[2][3] += a2 * b.w;
            acc[3][0] += a3 * b.x; acc[3][1] += a3 * b.y; acc[3][2] += a3 * b.z; acc[3][3] += a3 * b.w;
        }
        __syncthreads();
    }
#pragma unroll
    for (int i = 0; i < 4; i++) {
        int r = row0 + ty * 4 + i;
        if (r < NN) {
            float4 v = make_float4(acc[i][0], acc[i][1], acc[i][2], acc[i][3]);
            *(float4*)&g_xw[r * NH + tx * 4] = v;
        }
    }
}

// deg1[dst] += w ; deg2[dst] += 1
__global__ void k_deg(const int* __restrict__ ei, const float* __restrict__ ew, int E) {
    int e = blockIdx.x * blockDim.x + threadIdx.x;
    if (e >= E) return;
    int d = ei[E + e];
    atomicAdd(&g_deg1[d], ew[e]);
    atomicAdd(&g_deg2[d], 1.f);
}

__global__ void k_rsqrt() {
    int i = blockIdx.x * blockDim.x + threadIdx.x;
    if (i >= NN) return;
    float a = g_deg1[i];
    g_deg1[i] = (a > 0.f) ? rsqrtf(a) : 0.f;
    float b = g_deg2[i];
    g_deg2[i] = (b > 0.f) ? rsqrtf(b) : 0.f;
}

// conv1 message scatter: h[dst] += xw[src] * (dinv1[src]*w*dinv1[dst])
// 16 threads per edge, one float4 feature chunk each
__global__ void k_edge_msg(const int* __restrict__ ei, const float* __restrict__ ew, int E) {
    int tid = blockIdx.x * blockDim.x + threadIdx.x;
    int e = tid >> 4;
    if (e >= E) return;
    int q = tid & 15;
    int s = ei[e];
    int d = ei[E + e];
    float norm = g_deg1[s] * ew[e] * g_deg1[d];
    float4 v = ((const float4*)g_xw)[s * 16 + q];
    float* hp = g_h + d * NH + q * 4;
    atomicAdd(hp + 0, v.x * norm);
    atomicAdd(hp + 1, v.y * norm);
    atomicAdd(hp + 2, v.z * norm);
    atomicAdd(hp + 3, v.w * norm);
}

// self-loop + bias + relu, accumulate features into out_feat, compute hw = h.W2
// one warp per node, lane c handles features c and c+32
__global__ void k_node_fuse(const float* __restrict__ b1, const float* __restrict__ W2,
                            float* __restrict__ out_feat) {
    int gtid = blockIdx.x * blockDim.x + threadIdx.x;
    int node = gtid >> 5;
    int lane = threadIdx.x & 31;
    if (node >= NN) return;
    float di = g_deg1[node];
    float s = di * di;              // self-loop norm (w=1)
    float partial = 0.f;
#pragma unroll
    for (int t = 0; t < 2; t++) {
        int c = lane + t * 32;
        int idx = node * NH + c;
        float hv = g_h[idx] + g_xw[idx] * s + b1[c];
        hv = fmaxf(hv, 0.f);
        g_h[idx] = hv;
        out_feat[idx] += hv;        // sequential kernels: no race across views
        partial += hv * W2[c];
    }
#pragma unroll
    for (int o = 16; o > 0; o >>= 1)
        partial += __shfl_xor_sync(0xFFFFFFFFu, partial, o);
    if (lane == 0) g_hw[node] = partial;
}

// conv2 edge scatter (unit weights): out[dst] += hw[src]*dinv2[src]*dinv2[dst]
__global__ void k_edge2(const int* __restrict__ ei, float* __restrict__ out, int E) {
    int e = blockIdx.x * blockDim.x + threadIdx.x;
    if (e >= E) return;
    int s = ei[e];
    int d = ei[E + e];
    atomicAdd(&out[d], g_hw[s] * g_deg2[s] * g_deg2[d]);
}

// conv2 self-loop + bias
__global__ void k_node2(const float* __restrict__ b2, float* __restrict__ out) {
    int i = blockIdx.x * blockDim.x + threadIdx.x;
    if (i >= NN) return;
    float di = g_deg2[i];
    out[i] += g_hw[i] * di * di + b2[0];
}

extern "C" void kernel_launch(void* const* d_in, const int* in_sizes, int n_in,
                              void* d_out, int out_size) {
    const float* x = (const float*)d_in[0];
    const int*   ei[3] = {(const int*)d_in[1], (const int*)d_in[2], (const int*)d_in[3]};
    const float* ew[3] = {(const float*)d_in[4], (const float*)d_in[5], (const float*)d_in[6]};
    const float* W1[3] = {(const float*)d_in[7],  (const float*)d_in[11], (const float*)d_in[15]};
    const float* b1[3] = {(const float*)d_in[8],  (const float*)d_in[12], (const float*)d_in[16]};
    const float* W2[3] = {(const float*)d_in[9],  (const float*)d_in[13], (const float*)d_in[17]};
    const float* b2[3] = {(const float*)d_in[10], (const float*)d_in[14], (const float*)d_in[18]};
    float* out = (float*)d_out;
    int E = in_sizes[4];

    k_zero_out<<<(out_size + 255) / 256, 256>>>(out, out_size);

    for (int v = 0; v < 3; v++) {
        k_init_view<<<(NN * NH + 255) / 256, 256>>>();
        k_gemm<<<(NN + 63) / 64, 256>>>(x, W1[v]);
        k_deg<<<(E + 255) / 256, 256>>>(ei[v], ew[v], E);
        k_rsqrt<<<(NN + 255) / 256, 256>>>();
        long mt = (long)E * 16;
        k_edge_msg<<<(int)((mt + 255) / 256), 256>>>(ei[v], ew[v], E);
        k_node_fuse<<<(NN * 32 + 255) / 256, 256>>>(b1[v], W2[v], out + NN);
        k_edge2<<<(E + 255) / 256, 256>>>(ei[v], out, E);
        k_node2<<<(NN + 255) / 256, 256>>>(b2[v], out);
    }
}

// round 4
// speedup vs baseline: 1.2994x; 1.2994x over previous
#include <cuda_runtime.h>

#define NN 50000
#define FIN 256
#define NH 64

// Scratch (allocation-free rule: __device__ globals)
__device__ float g_xw[3 * NN * NH];    // x @ W1 per view
__device__ float g_h[3 * NN * NH];     // hidden accumulator per view (init by gemm epilogue)
__device__ float g_degv[3 * NN * 2];   // interleaved {weighted deg, count deg} per view
__device__ float g_dinv1[3 * NN];
__device__ float g_dinv2[3 * NN];
__device__ float g_hw[3 * NN];         // h @ W2 per node per view

__device__ __forceinline__ void red_v4(float* p, float a, float b, float c, float d) {
    asm volatile("red.global.add.v4.f32 [%0], {%1,%2,%3,%4};"
                 :: "l"(p), "f"(a), "f"(b), "f"(c), "f"(d) : "memory");
}
__device__ __forceinline__ void red_v2(float* p, float a, float b) {
    asm volatile("red.global.add.v2.f32 [%0], {%1,%2};"
                 :: "l"(p), "f"(a), "f"(b) : "memory");
}

// zero out[0:NN] and deg scratch (must re-zero every replay)
__global__ void k_zero(float* out) {
    int i = blockIdx.x * blockDim.x + threadIdx.x;
    if (i < NN) out[i] = 0.f;
    if (i < 3 * NN * 2) g_degv[i] = 0.f;
}

// degree accumulation, one thread per edge, grid.y = view
__global__ void k_deg(const int* __restrict__ e0, const int* __restrict__ e1, const int* __restrict__ e2,
                      const float* __restrict__ w0, const float* __restrict__ w1, const float* __restrict__ w2,
                      int E) {
    int e = blockIdx.x * blockDim.x + threadIdx.x;
    if (e >= E) return;
    int v = blockIdx.y;
    const int* ei = v == 0 ? e0 : v == 1 ? e1 : e2;
    const float* ew = v == 0 ? w0 : v == 1 ? w1 : w2;
    int d = ei[E + e];
    red_v2(&g_degv[(v * NN + d) * 2], ew[e], 1.f);
}

__global__ void k_rsqrt() {
    int i = blockIdx.x * blockDim.x + threadIdx.x;
    if (i >= NN) return;
    int v = blockIdx.y;
    int gi = v * NN + i;
    float a = 1.f + g_degv[gi * 2 + 0];   // +1: self-loop weight
    float b = 1.f + g_degv[gi * 2 + 1];
    g_dinv1[gi] = rsqrtf(a);
    g_dinv2[gi] = rsqrtf(b);
}

// xw = x @ W1 for all 3 views (grid.y = view), 128x64 tile, 8x4 register tile.
// Epilogue writes g_xw and g_h = xw * selfnorm (needs dinv1 ready).
__global__ void k_gemm3(const float* __restrict__ x,
                        const float* __restrict__ W1a, const float* __restrict__ W1b,
                        const float* __restrict__ W1c) {
    int v = blockIdx.y;
    const float* W = v == 0 ? W1a : v == 1 ? W1b : W1c;
    __shared__ float xs[128][36];   // [row][k], padded
    __shared__ float ws[32][64];    // [k][col]
    int tid = threadIdx.x;
    int row0 = blockIdx.x * 128;
    int tx = tid & 15;   // 4 cols
    int ty = tid >> 4;   // 8 rows
    float acc[8][4];
#pragma unroll
    for (int i = 0; i < 8; i++)
#pragma unroll
        for (int j = 0; j < 4; j++) acc[i][j] = 0.f;

    for (int kc = 0; kc < FIN; kc += 32) {
#pragma unroll
        for (int j = 0; j < 4; j++) {
            int idx = tid + j * 256;      // 0..1023
            int r = idx >> 3, f4 = idx & 7;
            int gr = row0 + r;
            float4 xv = make_float4(0.f, 0.f, 0.f, 0.f);
            if (gr < NN) xv = *(const float4*)&x[gr * FIN + kc + f4 * 4];
            *(float4*)&xs[r][f4 * 4] = xv;
        }
#pragma unroll
        for (int j = 0; j < 2; j++) {
            int idx = tid + j * 256;      // 0..511
            int kr = idx >> 4, c4 = idx & 15;
            *(float4*)&ws[kr][c4 * 4] = *(const float4*)&W[(kc + kr) * NH + c4 * 4];
        }
        __syncthreads();
#pragma unroll
        for (int k = 0; k < 32; k++) {
            float4 b = *(const float4*)&ws[k][tx * 4];
#pragma unroll
            for (int i = 0; i < 8; i++) {
                float a = xs[ty * 8 + i][k];
                acc[i][0] += a * b.x; acc[i][1] += a * b.y;
                acc[i][2] += a * b.z; acc[i][3] += a * b.w;
            }
        }
        __syncthreads();
    }
    size_t vb = (size_t)v * NN * NH;
#pragma unroll
    for (int i = 0; i < 8; i++) {
        int r = row0 + ty * 8 + i;
        if (r < NN) {
            float di = g_dinv1[v * NN + r];
            float sn = di * di;
            float4 o = make_float4(acc[i][0], acc[i][1], acc[i][2], acc[i][3]);
            *(float4*)&g_xw[vb + r * NH + tx * 4] = o;
            float4 hh = make_float4(o.x * sn, o.y * sn, o.z * sn, o.w * sn);
            *(float4*)&g_h[vb + r * NH + tx * 4] = hh;
        }
    }
}

// conv1 message scatter: h[dst] += xw[src]*norm ; 16 lanes per edge, v4 red atomics
__global__ void k_edge_msg(const int* __restrict__ e0, const int* __restrict__ e1, const int* __restrict__ e2,
                           const float* __restrict__ w0, const float* __restrict__ w1, const float* __restrict__ w2,
                           int E) {
    int tid = blockIdx.x * blockDim.x + threadIdx.x;
    int e = tid >> 4;
    if (e >= E) return;
    int v = blockIdx.y;
    const int* ei = v == 0 ? e0 : v == 1 ? e1 : e2;
    const float* ew = v == 0 ? w0 : v == 1 ? w1 : w2;
    int q = tid & 15;
    int s = 0, d = 0;
    float norm = 0.f;
    if (q == 0) {
        s = ei[e];
        d = ei[E + e];
        norm = g_dinv1[v * NN + s] * ew[e] * g_dinv1[v * NN + d];
    }
    s = __shfl_sync(0xFFFFFFFFu, s, 0, 16);
    d = __shfl_sync(0xFFFFFFFFu, d, 0, 16);
    norm = __shfl_sync(0xFFFFFFFFu, norm, 0, 16);
    size_t vb = (size_t)v * NN * NH;
    float4 xv = *(const float4*)&g_xw[vb + s * NH + q * 4];
    red_v4(&g_h[vb + d * NH + q * 4], xv.x * norm, xv.y * norm, xv.z * norm, xv.w * norm);
}

// per-node: bias+relu for all 3 views, sum features -> out_feat, hw = h.W2 per view
// one warp per node; lane c covers features c and c+32
__global__ void k_node_fuse(const float* __restrict__ b1a, const float* __restrict__ b1b, const float* __restrict__ b1c,
                            const float* __restrict__ W2a, const float* __restrict__ W2b, const float* __restrict__ W2c,
                            float* __restrict__ out_feat) {
    int gtid = blockIdx.x * blockDim.x + threadIdx.x;
    int node = gtid >> 5;
    int lane = threadIdx.x & 31;
    if (node >= NN) return;
    float f0 = 0.f, f1 = 0.f;
    float p[3];
#pragma unroll
    for (int v = 0; v < 3; v++) {
        const float* b1 = v == 0 ? b1a : v == 1 ? b1b : b1c;
        const float* W2 = v == 0 ? W2a : v == 1 ? W2b : W2c;
        size_t vb = (size_t)v * NN * NH;
        int c0 = lane, c1 = lane + 32;
        float h0 = fmaxf(g_h[vb + node * NH + c0] + b1[c0], 0.f);
        float h1 = fmaxf(g_h[vb + node * NH + c1] + b1[c1], 0.f);
        f0 += h0; f1 += h1;
        p[v] = h0 * W2[c0] + h1 * W2[c1];
    }
#pragma unroll
    for (int o = 16; o > 0; o >>= 1) {
        p[0] += __shfl_xor_sync(0xFFFFFFFFu, p[0], o);
        p[1] += __shfl_xor_sync(0xFFFFFFFFu, p[1], o);
        p[2] += __shfl_xor_sync(0xFFFFFFFFu, p[2], o);
    }
    if (lane == 0) {
        g_hw[0 * NN + node] = p[0];
        g_hw[1 * NN + node] = p[1];
        g_hw[2 * NN + node] = p[2];
    }
    out_feat[node * NH + lane] = f0;
    out_feat[node * NH + lane + 32] = f1;
}

// conv2 edge scatter (unit weights): out[dst] += hw[src]*dinv2[src]*dinv2[dst]
__global__ void k_edge2(const int* __restrict__ e0, const int* __restrict__ e1, const int* __restrict__ e2,
                        float* __restrict__ out, int E) {
    int e = blockIdx.x * blockDim.x + threadIdx.x;
    if (e >= E) return;
    int v = blockIdx.y;
    const int* ei = v == 0 ? e0 : v == 1 ? e1 : e2;
    int s = ei[e];
    int d = ei[E + e];
    atomicAdd(&out[d], g_hw[v * NN + s] * g_dinv2[v * NN + s] * g_dinv2[v * NN + d]);
}

// conv2 self-loop + bias for all views
__global__ void k_node2(const float* __restrict__ b2a, const float* __restrict__ b2b, const float* __restrict__ b2c,
                        float* __restrict__ out) {
    int i = blockIdx.x * blockDim.x + threadIdx.x;
    if (i >= NN) return;
    float acc = out[i];
#pragma unroll
    for (int v = 0; v < 3; v++) {
        const float* b2 = v == 0 ? b2a : v == 1 ? b2b : b2c;
        float di = g_dinv2[v * NN + i];
        acc += g_hw[v * NN + i] * di * di + b2[0];
    }
    out[i] = acc;
}

extern "C" void kernel_launch(void* const* d_in, const int* in_sizes, int n_in,
                              void* d_out, int out_size) {
    const float* x = (const float*)d_in[0];
    const int* e0 = (const int*)d_in[1];
    const int* e1 = (const int*)d_in[2];
    const int* e2 = (const int*)d_in[3];
    const float* w0 = (const float*)d_in[4];
    const float* w1 = (const float*)d_in[5];
    const float* w2 = (const float*)d_in[6];
    const float* W1a = (const float*)d_in[7];
    const float* b1a = (const float*)d_in[8];
    const float* W2a = (const float*)d_in[9];
    const float* b2a = (const float*)d_in[10];
    const float* W1b = (const float*)d_in[11];
    const float* b1b = (const float*)d_in[12];
    const float* W2b = (const float*)d_in[13];
    const float* b2b = (const float*)d_in[14];
    const float* W1c = (const float*)d_in[15];
    const float* b1c = (const float*)d_in[16];
    const float* W2c = (const float*)d_in[17];
    const float* b2c = (const float*)d_in[18];
    float* out = (float*)d_out;
    int E = in_sizes[4];

    k_zero<<<(3 * NN * 2 + 255) / 256, 256>>>(out);

    dim3 gdeg((E + 255) / 256, 3);
    k_deg<<<gdeg, 256>>>(e0, e1, e2, w0, w1, w2, E);

    dim3 grs((NN + 255) / 256, 3);
    k_rsqrt<<<grs, 256>>>();

    dim3 ggemm((NN + 127) / 128, 3);
    k_gemm3<<<ggemm, 256>>>(x, W1a, W1b, W1c);

    long mt = (long)E * 16;
    dim3 gmsg((unsigned)((mt + 255) / 256), 3);
    k_edge_msg<<<gmsg, 256>>>(e0, e1, e2, w0, w1, w2, E);

    k_node_fuse<<<(NN * 32 + 255) / 256, 256>>>(b1a, b1b, b1c, W2a, W2b, W2c, out + NN);

    dim3 ge2((E + 255) / 256, 3);
    k_edge2<<<ge2, 256>>>(e0, e1, e2, out, E);

    k_node2<<<(NN + 255) / 256, 256>>>(b2a, b2b, b2c, out);
}

// round 5
// speedup vs baseline: 1.8019x; 1.3867x over previous
#include <cuda_runtime.h>

#define NN 50000
#define FIN 256
#define NH 64
#define EMAX 800000

// Scratch (allocation-free rule: __device__ globals)
__device__ float g_xw[3 * NN * NH];     // x @ W1 per view
__device__ float g_degw[3 * NN];        // weighted in-degree (excl self)
__device__ int   g_cnt[3 * NN];         // in-edge count (excl self)
__device__ int   g_off[3 * (NN + 1)];   // CSR offsets per view
__device__ int   g_cur[3 * NN];         // fill cursors
__device__ int   g_src[3 * EMAX];       // CSR: src node per in-edge
__device__ float g_nrm[3 * EMAX];       // CSR: conv1 norm per in-edge
__device__ float g_dinv1[3 * NN];
__device__ float g_dinv2[3 * NN];
__device__ float g_hws[3 * NN];         // (h @ W2) * dinv2

__global__ void k_zero() {
    int i = blockIdx.x * blockDim.x + threadIdx.x;
    if (i < 3 * NN) { g_degw[i] = 0.f; g_cnt[i] = 0; }
}

// histogram + weighted degree
__global__ void k_deg(const int* __restrict__ e0, const int* __restrict__ e1, const int* __restrict__ e2,
                      const float* __restrict__ w0, const float* __restrict__ w1, const float* __restrict__ w2,
                      int E) {
    int e = blockIdx.x * blockDim.x + threadIdx.x;
    if (e >= E) return;
    int v = blockIdx.y;
    const int* ei = v == 0 ? e0 : v == 1 ? e1 : e2;
    const float* ew = v == 0 ? w0 : v == 1 ? w1 : w2;
    int d = ei[E + e];
    atomicAdd(&g_degw[v * NN + d], ew[e]);
    atomicAdd(&g_cnt[v * NN + d], 1);
}

// per-view exclusive prefix sum of counts -> offsets + cursors (1 block per view)
__global__ void k_scan() {
    __shared__ int part[1024];
    int v = blockIdx.x;
    int t = threadIdx.x;
    const int per = (NN + 1023) / 1024;
    int base = t * per;
    int sum = 0;
    for (int i = 0; i < per; i++) {
        int idx = base + i;
        if (idx < NN) sum += g_cnt[v * NN + idx];
    }
    part[t] = sum;
    __syncthreads();
    for (int o = 1; o < 1024; o <<= 1) {
        int val = 0;
        if (t >= o) val = part[t - o];
        __syncthreads();
        if (t >= o) part[t] += val;
        __syncthreads();
    }
    int run = (t == 0) ? 0 : part[t - 1];
    for (int i = 0; i < per; i++) {
        int idx = base + i;
        if (idx < NN) {
            g_off[v * (NN + 1) + idx] = run;
            g_cur[v * NN + idx] = run;
            run += g_cnt[v * NN + idx];
        }
    }
    if (t == 1023) g_off[v * (NN + 1) + NN] = run;
}

__global__ void k_rsqrt() {
    int i = blockIdx.x * blockDim.x + threadIdx.x;
    if (i >= NN) return;
    int v = blockIdx.y;
    int gi = v * NN + i;
    g_dinv1[gi] = rsqrtf(1.f + g_degw[gi]);
    g_dinv2[gi] = rsqrtf(1.f + (float)g_cnt[gi]);
}

// CSR fill: src + precomputed conv1 norm
__global__ void k_fill(const int* __restrict__ e0, const int* __restrict__ e1, const int* __restrict__ e2,
                       const float* __restrict__ w0, const float* __restrict__ w1, const float* __restrict__ w2,
                       int E) {
    int e = blockIdx.x * blockDim.x + threadIdx.x;
    if (e >= E) return;
    int v = blockIdx.y;
    const int* ei = v == 0 ? e0 : v == 1 ? e1 : e2;
    const float* ew = v == 0 ? w0 : v == 1 ? w1 : w2;
    int s = ei[e];
    int d = ei[E + e];
    int pos = atomicAdd(&g_cur[v * NN + d], 1);
    g_src[v * EMAX + pos] = s;
    g_nrm[v * EMAX + pos] = g_dinv1[v * NN + s] * ew[e] * g_dinv1[v * NN + d];
}

// xw = x @ W1 for all 3 views (grid.y = view), 128x64 tile, 8x4 register tile
__global__ void k_gemm3(const float* __restrict__ x,
                        const float* __restrict__ W1a, const float* __restrict__ W1b,
                        const float* __restrict__ W1c) {
    int v = blockIdx.y;
    const float* W = v == 0 ? W1a : v == 1 ? W1b : W1c;
    __shared__ float xs[128][36];   // [row][k], padded
    __shared__ float ws[32][64];    // [k][col]
    int tid = threadIdx.x;
    int row0 = blockIdx.x * 128;
    int tx = tid & 15;
    int ty = tid >> 4;
    float acc[8][4];
#pragma unroll
    for (int i = 0; i < 8; i++)
#pragma unroll
        for (int j = 0; j < 4; j++) acc[i][j] = 0.f;

    for (int kc = 0; kc < FIN; kc += 32) {
#pragma unroll
        for (int j = 0; j < 4; j++) {
            int idx = tid + j * 256;
            int r = idx >> 3, f4 = idx & 7;
            int gr = row0 + r;
            float4 xv = make_float4(0.f, 0.f, 0.f, 0.f);
            if (gr < NN) xv = *(const float4*)&x[gr * FIN + kc + f4 * 4];
            *(float4*)&xs[r][f4 * 4] = xv;
        }
#pragma unroll
        for (int j = 0; j < 2; j++) {
            int idx = tid + j * 256;
            int kr = idx >> 4, c4 = idx & 15;
            *(float4*)&ws[kr][c4 * 4] = *(const float4*)&W[(kc + kr) * NH + c4 * 4];
        }
        __syncthreads();
#pragma unroll
        for (int k = 0; k < 32; k++) {
            float4 b = *(const float4*)&ws[k][tx * 4];
#pragma unroll
            for (int i = 0; i < 8; i++) {
                float a = xs[ty * 8 + i][k];
                acc[i][0] += a * b.x; acc[i][1] += a * b.y;
                acc[i][2] += a * b.z; acc[i][3] += a * b.w;
            }
        }
        __syncthreads();
    }
    size_t vb = (size_t)v * NN * NH;
#pragma unroll
    for (int i = 0; i < 8; i++) {
        int r = row0 + ty * 8 + i;
        if (r < NN) {
            float4 o = make_float4(acc[i][0], acc[i][1], acc[i][2], acc[i][3]);
            *(float4*)&g_xw[vb + r * NH + tx * 4] = o;
        }
    }
}

// conv1 pull + epilogue: warp = 2 dst nodes, 16 lanes x float4 features.
// Per (node): for each view accumulate in-edge messages + self term, add b1,
// ReLU, sum features across views -> out_feat, reduce h.W2 -> g_hws.
__global__ void k_gather1(const float* __restrict__ b1a, const float* __restrict__ b1b, const float* __restrict__ b1c,
                          const float* __restrict__ W2a, const float* __restrict__ W2b, const float* __restrict__ W2c,
                          float* __restrict__ out_feat) {
    int gtid = blockIdx.x * blockDim.x + threadIdx.x;
    int node = gtid >> 4;           // 16 threads per node
    if (node >= NN) return;
    int q = threadIdx.x & 15;       // float4 chunk index
    const float4* xw4 = (const float4*)g_xw;

    float4 fo = make_float4(0.f, 0.f, 0.f, 0.f);
    float dot[3];
#pragma unroll
    for (int v = 0; v < 3; v++) {
        const float* b1 = v == 0 ? b1a : v == 1 ? b1b : b1c;
        const float* W2 = v == 0 ? W2a : v == 1 ? W2b : W2c;
        int beg = g_off[v * (NN + 1) + node];
        int end = g_off[v * (NN + 1) + node + 1];
        const int* sp = g_src + v * EMAX;
        const float* np = g_nrm + v * EMAX;
        size_t vb16 = (size_t)v * NN * 16;
        float4 a = make_float4(0.f, 0.f, 0.f, 0.f);
#pragma unroll 4
        for (int j = beg; j < end; j++) {
            int s = sp[j];
            float nm = np[j];
            float4 xv = xw4[vb16 + s * 16 + q];
            a.x += nm * xv.x; a.y += nm * xv.y; a.z += nm * xv.z; a.w += nm * xv.w;
        }
        // self loop
        float di = g_dinv1[v * NN + node];
        float sn = di * di;
        float4 xs = xw4[vb16 + node * 16 + q];
        float4 bv = *(const float4*)&b1[q * 4];
        float4 h;
        h.x = fmaxf(a.x + xs.x * sn + bv.x, 0.f);
        h.y = fmaxf(a.y + xs.y * sn + bv.y, 0.f);
        h.z = fmaxf(a.z + xs.z * sn + bv.z, 0.f);
        h.w = fmaxf(a.w + xs.w * sn + bv.w, 0.f);
        fo.x += h.x; fo.y += h.y; fo.z += h.z; fo.w += h.w;
        float4 w2 = *(const float4*)&W2[q * 4];
        dot[v] = h.x * w2.x + h.y * w2.y + h.z * w2.z + h.w * w2.w;
    }
    // reduce dot over the 16 lanes of this node
#pragma unroll
    for (int o = 8; o > 0; o >>= 1) {
        dot[0] += __shfl_xor_sync(0xFFFFFFFFu, dot[0], o);
        dot[1] += __shfl_xor_sync(0xFFFFFFFFu, dot[1], o);
        dot[2] += __shfl_xor_sync(0xFFFFFFFFu, dot[2], o);
    }
    if (q == 0) {
#pragma unroll
        for (int v = 0; v < 3; v++)
            g_hws[v * NN + node] = dot[v] * g_dinv2[v * NN + node];
    }
    *(float4*)&out_feat[node * NH + q * 4] = fo;
}

// conv2 pull: out[i] = sum_v ( dinv2_v[i] * sum_in hws_v[src] + hws_v[i]*dinv2_v[i] + b2_v )
__global__ void k_gather2(const float* __restrict__ b2a, const float* __restrict__ b2b, const float* __restrict__ b2c,
                          float* __restrict__ out) {
    int i = blockIdx.x * blockDim.x + threadIdx.x;
    if (i >= NN) return;
    float acc = 0.f;
#pragma unroll
    for (int v = 0; v < 3; v++) {
        const float* b2 = v == 0 ? b2a : v == 1 ? b2b : b2c;
        int beg = g_off[v * (NN + 1) + i];
        int end = g_off[v * (NN + 1) + i + 1];
        const int* sp = g_src + v * EMAX;
        float t = 0.f;
#pragma unroll 8
        for (int j = beg; j < end; j++)
            t += g_hws[v * NN + sp[j]];
        float di = g_dinv2[v * NN + i];
        acc += di * t + g_hws[v * NN + i] * di + b2[0];
    }
    out[i] = acc;
}

extern "C" void kernel_launch(void* const* d_in, const int* in_sizes, int n_in,
                              void* d_out, int out_size) {
    const float* x = (const float*)d_in[0];
    const int* e0 = (const int*)d_in[1];
    const int* e1 = (const int*)d_in[2];
    const int* e2 = (const int*)d_in[3];
    const float* w0 = (const float*)d_in[4];
    const float* w1 = (const float*)d_in[5];
    const float* w2 = (const float*)d_in[6];
    const float* W1a = (const float*)d_in[7];
    const float* b1a = (const float*)d_in[8];
    const float* W2a = (const float*)d_in[9];
    const float* b2a = (const float*)d_in[10];
    const float* W1b = (const float*)d_in[11];
    const float* b1b = (const float*)d_in[12];
    const float* W2b = (const float*)d_in[13];
    const float* b2b = (const float*)d_in[14];
    const float* W1c = (const float*)d_in[15];
    const float* b1c = (const float*)d_in[16];
    const float* W2c = (const float*)d_in[17];
    const float* b2c = (const float*)d_in[18];
    float* out = (float*)d_out;
    int E = in_sizes[4];

    k_zero<<<(3 * NN + 255) / 256, 256>>>();

    dim3 gedge((E + 255) / 256, 3);
    k_deg<<<gedge, 256>>>(e0, e1, e2, w0, w1, w2, E);

    k_scan<<<3, 1024>>>();

    dim3 grs((NN + 255) / 256, 3);
    k_rsqrt<<<grs, 256>>>();

    k_fill<<<gedge, 256>>>(e0, e1, e2, w0, w1, w2, E);

    dim3 ggemm((NN + 127) / 128, 3);
    k_gemm3<<<ggemm, 256>>>(x, W1a, W1b, W1c);

    k_gather1<<<(NN * 16 + 255) / 256, 256>>>(b1a, b1b, b1c, W2a, W2b, W2c, out + NN);

    k_gather2<<<(NN + 255) / 256, 256>>>(b2a, b2b, b2c, out);
}

// round 6
// speedup vs baseline: 2.1441x; 1.1899x over previous
#include <cuda_runtime.h>
#include <cstdint>

#define NN 50000
#define FIN 256
#define NH 64
#define EMAX 800000

// Scratch (allocation-free rule: __device__ globals)
__device__ float g_xw[3 * NN * NH];     // x @ W1 per view
__device__ float g_degw[3 * NN];        // weighted in-degree (excl self)
__device__ int   g_cnt[3 * NN];         // in-edge count (excl self)
__device__ int   g_off[3 * (NN + 1)];   // CSR offsets per view
__device__ int   g_cur[3 * NN];         // fill cursors
__device__ int   g_src[3 * EMAX];       // CSR: src node per in-edge
__device__ float g_nrm[3 * EMAX];       // CSR: conv1 norm per in-edge
__device__ float g_dinv1[3 * NN];
__device__ float g_dinv2[3 * NN];
__device__ float g_hws[3 * NN];         // (h @ W2) * dinv2

__device__ __forceinline__ uint32_t to_tf32(float f) {
    uint32_t r;
    asm("cvt.rna.tf32.f32 %0, %1;" : "=r"(r) : "f"(f));
    return r;
}

__global__ void k_zero() {
    int i = blockIdx.x * blockDim.x + threadIdx.x;
    if (i < 3 * NN) { g_degw[i] = 0.f; g_cnt[i] = 0; }
}

// histogram + weighted degree
__global__ void k_deg(const int* __restrict__ e0, const int* __restrict__ e1, const int* __restrict__ e2,
                      const float* __restrict__ w0, const float* __restrict__ w1, const float* __restrict__ w2,
                      int E) {
    int e = blockIdx.x * blockDim.x + threadIdx.x;
    if (e >= E) return;
    int v = blockIdx.y;
    const int* ei = v == 0 ? e0 : v == 1 ? e1 : e2;
    const float* ew = v == 0 ? w0 : v == 1 ? w1 : w2;
    int d = ei[E + e];
    atomicAdd(&g_degw[v * NN + d], ew[e]);
    atomicAdd(&g_cnt[v * NN + d], 1);
}

// per-view exclusive prefix sum of counts -> offsets + cursors (1 block per view)
__global__ void k_scan() {
    __shared__ int part[1024];
    int v = blockIdx.x;
    int t = threadIdx.x;
    const int per = (NN + 1023) / 1024;
    int base = t * per;
    int sum = 0;
    for (int i = 0; i < per; i++) {
        int idx = base + i;
        if (idx < NN) sum += g_cnt[v * NN + idx];
    }
    part[t] = sum;
    __syncthreads();
    for (int o = 1; o < 1024; o <<= 1) {
        int val = 0;
        if (t >= o) val = part[t - o];
        __syncthreads();
        if (t >= o) part[t] += val;
        __syncthreads();
    }
    int run = (t == 0) ? 0 : part[t - 1];
    for (int i = 0; i < per; i++) {
        int idx = base + i;
        if (idx < NN) {
            g_off[v * (NN + 1) + idx] = run;
            g_cur[v * NN + idx] = run;
            run += g_cnt[v * NN + idx];
        }
    }
    if (t == 1023) g_off[v * (NN + 1) + NN] = run;
}

__global__ void k_rsqrt() {
    int i = blockIdx.x * blockDim.x + threadIdx.x;
    if (i >= NN) return;
    int v = blockIdx.y;
    int gi = v * NN + i;
    g_dinv1[gi] = rsqrtf(1.f + g_degw[gi]);
    g_dinv2[gi] = rsqrtf(1.f + (float)g_cnt[gi]);
}

// CSR fill: src + precomputed conv1 norm
__global__ void k_fill(const int* __restrict__ e0, const int* __restrict__ e1, const int* __restrict__ e2,
                       const float* __restrict__ w0, const float* __restrict__ w1, const float* __restrict__ w2,
                       int E) {
    int e = blockIdx.x * blockDim.x + threadIdx.x;
    if (e >= E) return;
    int v = blockIdx.y;
    const int* ei = v == 0 ? e0 : v == 1 ? e1 : e2;
    const float* ew = v == 0 ? w0 : v == 1 ? w1 : w2;
    int s = ei[e];
    int d = ei[E + e];
    int pos = atomicAdd(&g_cur[v * NN + d], 1);
    g_src[v * EMAX + pos] = s;
    g_nrm[v * EMAX + pos] = g_dinv1[v * NN + s] * ew[e] * g_dinv1[v * NN + d];
}

// xw = x @ W1 for all 3 views via tf32 mma.sync.m16n8k8.
// Block: 256 threads = 8 warps; tile M=128 (16 rows/warp), N=64, k-chunk 32.
__global__ void k_gemm3(const float* __restrict__ x,
                        const float* __restrict__ W1a, const float* __restrict__ W1b,
                        const float* __restrict__ W1c) {
    int v = blockIdx.y;
    const float* W = v == 0 ? W1a : v == 1 ? W1b : W1c;
    __shared__ uint32_t xs[128][36];   // [row][k] tf32, stride 36 -> bank = 4g+t (conflict-free)
    __shared__ uint32_t ws[32][68];    // [k][col] tf32, stride 68 -> bank = 4t+g (conflict-free)
    int tid  = threadIdx.x;
    int wid  = tid >> 5;
    int lane = tid & 31;
    int g = lane >> 2;     // groupID (0..7)
    int t = lane & 3;      // threadID_in_group (0..3)
    int row0 = blockIdx.x * 128;
    int wr = wid * 16;     // warp row base within tile

    float c[8][4];
#pragma unroll
    for (int nt = 0; nt < 8; nt++)
#pragma unroll
        for (int i = 0; i < 4; i++) c[nt][i] = 0.f;

    for (int kc = 0; kc < FIN; kc += 32) {
        // stage x tile: 128 rows x 32 k (1024 float4)
#pragma unroll
        for (int j = 0; j < 4; j++) {
            int idx = tid + j * 256;
            int r = idx >> 3, f4 = idx & 7;
            int gr = row0 + r;
            float4 xv = make_float4(0.f, 0.f, 0.f, 0.f);
            if (gr < NN) xv = *(const float4*)&x[gr * FIN + kc + f4 * 4];
            uint32_t* p = &xs[r][f4 * 4];
            p[0] = to_tf32(xv.x); p[1] = to_tf32(xv.y);
            p[2] = to_tf32(xv.z); p[3] = to_tf32(xv.w);
        }
        // stage W tile: 32 k x 64 cols (512 float4)
#pragma unroll
        for (int j = 0; j < 2; j++) {
            int idx = tid + j * 256;
            int kr = idx >> 4, c4 = idx & 15;
            float4 wv = *(const float4*)&W[(kc + kr) * NH + c4 * 4];
            uint32_t* p = &ws[kr][c4 * 4];
            p[0] = to_tf32(wv.x); p[1] = to_tf32(wv.y);
            p[2] = to_tf32(wv.z); p[3] = to_tf32(wv.w);
        }
        __syncthreads();
#pragma unroll
        for (int k0 = 0; k0 < 32; k0 += 8) {
            uint32_t a0 = xs[wr + g][k0 + t];
            uint32_t a1 = xs[wr + g + 8][k0 + t];
            uint32_t a2 = xs[wr + g][k0 + t + 4];
            uint32_t a3 = xs[wr + g + 8][k0 + t + 4];
#pragma unroll
            for (int nt = 0; nt < 8; nt++) {
                uint32_t b0 = ws[k0 + t][nt * 8 + g];
                uint32_t b1 = ws[k0 + t + 4][nt * 8 + g];
                asm volatile(
                    "mma.sync.aligned.m16n8k8.row.col.f32.tf32.tf32.f32 "
                    "{%0,%1,%2,%3}, {%4,%5,%6,%7}, {%8,%9}, {%0,%1,%2,%3};"
                    : "+f"(c[nt][0]), "+f"(c[nt][1]), "+f"(c[nt][2]), "+f"(c[nt][3])
                    : "r"(a0), "r"(a1), "r"(a2), "r"(a3), "r"(b0), "r"(b1));
            }
        }
        __syncthreads();
    }
    // epilogue: c{0,1}: row wr+g, cols nt*8 + 2t + {0,1}; c{2,3}: row wr+g+8
    size_t vb = (size_t)v * NN * NH;
    int r0 = row0 + wr + g;
    int r1 = r0 + 8;
#pragma unroll
    for (int nt = 0; nt < 8; nt++) {
        int col = nt * 8 + t * 2;
        if (r0 < NN) *(float2*)&g_xw[vb + (size_t)r0 * NH + col] = make_float2(c[nt][0], c[nt][1]);
        if (r1 < NN) *(float2*)&g_xw[vb + (size_t)r1 * NH + col] = make_float2(c[nt][2], c[nt][3]);
    }
}

// conv1 pull + epilogue: 16 lanes x float4 features per node.
__global__ void k_gather1(const float* __restrict__ b1a, const float* __restrict__ b1b, const float* __restrict__ b1c,
                          const float* __restrict__ W2a, const float* __restrict__ W2b, const float* __restrict__ W2c,
                          float* __restrict__ out_feat) {
    int gtid = blockIdx.x * blockDim.x + threadIdx.x;
    int node = gtid >> 4;           // 16 threads per node
    if (node >= NN) return;
    int q = threadIdx.x & 15;       // float4 chunk index
    const float4* xw4 = (const float4*)g_xw;

    float4 fo = make_float4(0.f, 0.f, 0.f, 0.f);
    float dot[3];
#pragma unroll
    for (int v = 0; v < 3; v++) {
        const float* b1 = v == 0 ? b1a : v == 1 ? b1b : b1c;
        const float* W2 = v == 0 ? W2a : v == 1 ? W2b : W2c;
        int beg = g_off[v * (NN + 1) + node];
        int end = g_off[v * (NN + 1) + node + 1];
        const int* sp = g_src + v * EMAX;
        const float* np = g_nrm + v * EMAX;
        size_t vb16 = (size_t)v * NN * 16;
        float4 a = make_float4(0.f, 0.f, 0.f, 0.f);
#pragma unroll 4
        for (int j = beg; j < end; j++) {
            int s = sp[j];
            float nm = np[j];
            float4 xv = xw4[vb16 + s * 16 + q];
            a.x += nm * xv.x; a.y += nm * xv.y; a.z += nm * xv.z; a.w += nm * xv.w;
        }
        // self loop
        float di = g_dinv1[v * NN + node];
        float sn = di * di;
        float4 xs = xw4[vb16 + node * 16 + q];
        float4 bv = *(const float4*)&b1[q * 4];
        float4 h;
        h.x = fmaxf(a.x + xs.x * sn + bv.x, 0.f);
        h.y = fmaxf(a.y + xs.y * sn + bv.y, 0.f);
        h.z = fmaxf(a.z + xs.z * sn + bv.z, 0.f);
        h.w = fmaxf(a.w + xs.w * sn + bv.w, 0.f);
        fo.x += h.x; fo.y += h.y; fo.z += h.z; fo.w += h.w;
        float4 w2 = *(const float4*)&W2[q * 4];
        dot[v] = h.x * w2.x + h.y * w2.y + h.z * w2.z + h.w * w2.w;
    }
#pragma unroll
    for (int o = 8; o > 0; o >>= 1) {
        dot[0] += __shfl_xor_sync(0xFFFFFFFFu, dot[0], o);
        dot[1] += __shfl_xor_sync(0xFFFFFFFFu, dot[1], o);
        dot[2] += __shfl_xor_sync(0xFFFFFFFFu, dot[2], o);
    }
    if (q == 0) {
#pragma unroll
        for (int v = 0; v < 3; v++)
            g_hws[v * NN + node] = dot[v] * g_dinv2[v * NN + node];
    }
    *(float4*)&out_feat[node * NH + q * 4] = fo;
}

// conv2 pull
__global__ void k_gather2(const float* __restrict__ b2a, const float* __restrict__ b2b, const float* __restrict__ b2c,
                          float* __restrict__ out) {
    int i = blockIdx.x * blockDim.x + threadIdx.x;
    if (i >= NN) return;
    float acc = 0.f;
#pragma unroll
    for (int v = 0; v < 3; v++) {
        const float* b2 = v == 0 ? b2a : v == 1 ? b2b : b2c;
        int beg = g_off[v * (NN + 1) + i];
        int end = g_off[v * (NN + 1) + i + 1];
        const int* sp = g_src + v * EMAX;
        float t = 0.f;
#pragma unroll 8
        for (int j = beg; j < end; j++)
            t += g_hws[v * NN + sp[j]];
        float di = g_dinv2[v * NN + i];
        acc += di * t + g_hws[v * NN + i] * di + b2[0];
    }
    out[i] = acc;
}

extern "C" void kernel_launch(void* const* d_in, const int* in_sizes, int n_in,
                              void* d_out, int out_size) {
    const float* x = (const float*)d_in[0];
    const int* e0 = (const int*)d_in[1];
    const int* e1 = (const int*)d_in[2];
    const int* e2 = (const int*)d_in[3];
    const float* w0 = (const float*)d_in[4];
    const float* w1 = (const float*)d_in[5];
    const float* w2 = (const float*)d_in[6];
    const float* W1a = (const float*)d_in[7];
    const float* b1a = (const float*)d_in[8];
    const float* W2a = (const float*)d_in[9];
    const float* b2a = (const float*)d_in[10];
    const float* W1b = (const float*)d_in[11];
    const float* b1b = (const float*)d_in[12];
    const float* W2b = (const float*)d_in[13];
    const float* b2b = (const float*)d_in[14];
    const float* W1c = (const float*)d_in[15];
    const float* b1c = (const float*)d_in[16];
    const float* W2c = (const float*)d_in[17];
    const float* b2c = (const float*)d_in[18];
    float* out = (float*)d_out;
    int E = in_sizes[4];

    k_zero<<<(3 * NN + 255) / 256, 256>>>();

    dim3 gedge((E + 255) / 256, 3);
    k_deg<<<gedge, 256>>>(e0, e1, e2, w0, w1, w2, E);

    k_scan<<<3, 1024>>>();

    dim3 grs((NN + 255) / 256, 3);
    k_rsqrt<<<grs, 256>>>();

    k_fill<<<gedge, 256>>>(e0, e1, e2, w0, w1, w2, E);

    dim3 ggemm((NN + 127) / 128, 3);
    k_gemm3<<<ggemm, 256>>>(x, W1a, W1b, W1c);

    k_gather1<<<(NN * 16 + 255) / 256, 256>>>(b1a, b1b, b1c, W2a, W2b, W2c, out + NN);

    k_gather2<<<(NN + 255) / 256, 256>>>(b2a, b2b, b2c, out);
}

// round 7
// speedup vs baseline: 3.1107x; 1.4508x over previous
#include <cuda_runtime.h>
#include <cuda_fp16.h>
#include <cstdint>

#define NN 50000
#define FIN 256
#define NH 64
#define EMAX 800000
#define SCAN_B 196            // blocks per view in hierarchical scan (196*256 >= 50000)

// Scratch (allocation-free rule: __device__ globals)
__device__ __half g_xwh[3 * NN * NH];   // x @ W1 per view (fp16 storage)
__device__ float g_degc[3 * NN * 2];    // interleaved {weighted deg, count} per node
__device__ int   g_off[3 * (NN + 1)];   // CSR offsets per view
__device__ int   g_cur[3 * NN];         // fill cursors
__device__ int2  g_csr[3 * EMAX];       // CSR: {src, float_bits(norm)} per in-edge
__device__ int   g_bsum[3 * SCAN_B];    // per-block count sums (scan level 1)
__device__ float g_dinv1[3 * NN];
__device__ float g_dinv2[3 * NN];
__device__ float g_hws[3 * NN];         // (h @ W2) * dinv2

__device__ __forceinline__ void red_v2(float* p, float a, float b) {
    asm volatile("red.global.add.v2.f32 [%0], {%1,%2};"
                 :: "l"(p), "f"(a), "f"(b) : "memory");
}
__device__ __forceinline__ uint32_t to_tf32(float f) {
    uint32_t r;
    asm("cvt.rna.tf32.f32 %0, %1;" : "=r"(r) : "f"(f));
    return r;
}

__global__ void k_zero() {
    int i = blockIdx.x * blockDim.x + threadIdx.x;
    if (i < 3 * NN * 2) g_degc[i] = 0.f;
}

// degree histogram: one vector red per edge
__global__ void k_deg(const int* __restrict__ e0, const int* __restrict__ e1, const int* __restrict__ e2,
                      const float* __restrict__ w0, const float* __restrict__ w1, const float* __restrict__ w2,
                      int E) {
    int e = blockIdx.x * blockDim.x + threadIdx.x;
    if (e >= E) return;
    int v = blockIdx.y;
    const int* ei = v == 0 ? e0 : v == 1 ? e1 : e2;
    const float* ew = v == 0 ? w0 : v == 1 ? w1 : w2;
    int d = ei[E + e];
    red_v2(&g_degc[(v * NN + d) * 2], ew[e], 1.f);
}

// scan level 1: per-block (256-node) count sums, coalesced
__global__ void k_scanA() {
    __shared__ int sm[8];
    int v = blockIdx.y;
    int idx = blockIdx.x * 256 + threadIdx.x;
    int c = (idx < NN) ? (int)g_degc[(v * NN + idx) * 2 + 1] : 0;
#pragma unroll
    for (int o = 16; o > 0; o >>= 1) c += __shfl_xor_sync(0xFFFFFFFFu, c, o);
    if ((threadIdx.x & 31) == 0) sm[threadIdx.x >> 5] = c;
    __syncthreads();
    if (threadIdx.x == 0) {
        int s = 0;
#pragma unroll
        for (int i = 0; i < 8; i++) s += sm[i];
        g_bsum[v * SCAN_B + blockIdx.x] = s;
    }
}

// scan level 2: exclusive scan of SCAN_B block sums per view; warp w handles view w
__global__ void k_scanB() {
    int w = threadIdx.x >> 5;
    int lane = threadIdx.x & 31;
    if (w >= 3) return;
    int run = 0;
    for (int base = 0; base < SCAN_B; base += 32) {
        int i = base + lane;
        int val = (i < SCAN_B) ? g_bsum[w * SCAN_B + i] : 0;
        int orig = val;
#pragma unroll
        for (int o = 1; o < 32; o <<= 1) {
            int y = __shfl_up_sync(0xFFFFFFFFu, val, o);
            if (lane >= o) val += y;
        }
        if (i < SCAN_B) g_bsum[w * SCAN_B + i] = run + val - orig;  // exclusive
        run += __shfl_sync(0xFFFFFFFFu, val, 31);
    }
}

// scan level 3: block-local exclusive scan + base; writes off, cur, dinv1, dinv2
__global__ void k_scanC(int E) {
    __shared__ int sm[256];
    int v = blockIdx.y;
    int idx = blockIdx.x * 256 + threadIdx.x;
    int t = threadIdx.x;
    float dw = 0.f;
    int c = 0;
    if (idx < NN) {
        dw = g_degc[(v * NN + idx) * 2 + 0];
        c  = (int)g_degc[(v * NN + idx) * 2 + 1];
    }
    sm[t] = c;
    __syncthreads();
    for (int o = 1; o < 256; o <<= 1) {
        int y = (t >= o) ? sm[t - o] : 0;
        __syncthreads();
        if (t >= o) sm[t] += y;
        __syncthreads();
    }
    if (idx < NN) {
        int base = g_bsum[v * SCAN_B + blockIdx.x];
        int off = base + sm[t] - c;    // exclusive
        g_off[v * (NN + 1) + idx] = off;
        g_cur[v * NN + idx] = off;
        g_dinv1[v * NN + idx] = rsqrtf(1.f + dw);
        g_dinv2[v * NN + idx] = rsqrtf(1.f + (float)c);
    }
    if (blockIdx.x == 0 && t == 0) g_off[v * (NN + 1) + NN] = E;
}

// CSR fill: packed {src, norm}
__global__ void k_fill(const int* __restrict__ e0, const int* __restrict__ e1, const int* __restrict__ e2,
                       const float* __restrict__ w0, const float* __restrict__ w1, const float* __restrict__ w2,
                       int E) {
    int e = blockIdx.x * blockDim.x + threadIdx.x;
    if (e >= E) return;
    int v = blockIdx.y;
    const int* ei = v == 0 ? e0 : v == 1 ? e1 : e2;
    const float* ew = v == 0 ? w0 : v == 1 ? w1 : w2;
    int s = ei[e];
    int d = ei[E + e];
    int pos = atomicAdd(&g_cur[v * NN + d], 1);
    float nrm = g_dinv1[v * NN + s] * ew[e] * g_dinv1[v * NN + d];
    g_csr[v * EMAX + pos] = make_int2(s, __float_as_int(nrm));
}

// xw = x @ W1 for all 3 views via tf32 mma.sync.m16n8k8; fp16 output.
__global__ void k_gemm3(const float* __restrict__ x,
                        const float* __restrict__ W1a, const float* __restrict__ W1b,
                        const float* __restrict__ W1c) {
    int v = blockIdx.y;
    const float* W = v == 0 ? W1a : v == 1 ? W1b : W1c;
    __shared__ uint32_t xs[128][36];   // [row][k] tf32
    __shared__ uint32_t ws[32][68];    // [k][col] tf32
    int tid  = threadIdx.x;
    int wid  = tid >> 5;
    int lane = tid & 31;
    int g = lane >> 2;
    int t = lane & 3;
    int row0 = blockIdx.x * 128;
    int wr = wid * 16;

    float c[8][4];
#pragma unroll
    for (int nt = 0; nt < 8; nt++)
#pragma unroll
        for (int i = 0; i < 4; i++) c[nt][i] = 0.f;

    for (int kc = 0; kc < FIN; kc += 32) {
#pragma unroll
        for (int j = 0; j < 4; j++) {
            int idx = tid + j * 256;
            int r = idx >> 3, f4 = idx & 7;
            int gr = row0 + r;
            float4 xv = make_float4(0.f, 0.f, 0.f, 0.f);
            if (gr < NN) xv = *(const float4*)&x[gr * FIN + kc + f4 * 4];
            uint32_t* p = &xs[r][f4 * 4];
            p[0] = to_tf32(xv.x); p[1] = to_tf32(xv.y);
            p[2] = to_tf32(xv.z); p[3] = to_tf32(xv.w);
        }
#pragma unroll
        for (int j = 0; j < 2; j++) {
            int idx = tid + j * 256;
            int kr = idx >> 4, c4 = idx & 15;
            float4 wv = *(const float4*)&W[(kc + kr) * NH + c4 * 4];
            uint32_t* p = &ws[kr][c4 * 4];
            p[0] = to_tf32(wv.x); p[1] = to_tf32(wv.y);
            p[2] = to_tf32(wv.z); p[3] = to_tf32(wv.w);
        }
        __syncthreads();
#pragma unroll
        for (int k0 = 0; k0 < 32; k0 += 8) {
            uint32_t a0 = xs[wr + g][k0 + t];
            uint32_t a1 = xs[wr + g + 8][k0 + t];
            uint32_t a2 = xs[wr + g][k0 + t + 4];
            uint32_t a3 = xs[wr + g + 8][k0 + t + 4];
#pragma unroll
            for (int nt = 0; nt < 8; nt++) {
                uint32_t b0 = ws[k0 + t][nt * 8 + g];
                uint32_t b1 = ws[k0 + t + 4][nt * 8 + g];
                asm volatile(
                    "mma.sync.aligned.m16n8k8.row.col.f32.tf32.tf32.f32 "
                    "{%0,%1,%2,%3}, {%4,%5,%6,%7}, {%8,%9}, {%0,%1,%2,%3};"
                    : "+f"(c[nt][0]), "+f"(c[nt][1]), "+f"(c[nt][2]), "+f"(c[nt][3])
                    : "r"(a0), "r"(a1), "r"(a2), "r"(a3), "r"(b0), "r"(b1));
            }
        }
        __syncthreads();
    }
    size_t vb = (size_t)v * NN * NH;
    int r0 = row0 + wr + g;
    int r1 = r0 + 8;
#pragma unroll
    for (int nt = 0; nt < 8; nt++) {
        int col = nt * 8 + t * 2;
        if (r0 < NN) *(__half2*)&g_xwh[vb + (size_t)r0 * NH + col] = __floats2half2_rn(c[nt][0], c[nt][1]);
        if (r1 < NN) *(__half2*)&g_xwh[vb + (size_t)r1 * NH + col] = __floats2half2_rn(c[nt][2], c[nt][3]);
    }
}

// conv1 pull + epilogue: 16 lanes per node, 4 features (fp16 loads) each.
__global__ void k_gather1(const float* __restrict__ b1a, const float* __restrict__ b1b, const float* __restrict__ b1c,
                          const float* __restrict__ W2a, const float* __restrict__ W2b, const float* __restrict__ W2c,
                          float* __restrict__ out_feat) {
    int gtid = blockIdx.x * blockDim.x + threadIdx.x;
    int node = gtid >> 4;
    if (node >= NN) return;
    int q = threadIdx.x & 15;

    float4 fo = make_float4(0.f, 0.f, 0.f, 0.f);
    float dot[3];
#pragma unroll
    for (int v = 0; v < 3; v++) {
        const float* b1 = v == 0 ? b1a : v == 1 ? b1b : b1c;
        const float* W2 = v == 0 ? W2a : v == 1 ? W2b : W2c;
        int beg = g_off[v * (NN + 1) + node];
        int end = g_off[v * (NN + 1) + node + 1];
        const int2* cp = g_csr + v * EMAX;
        const __half* xwp = g_xwh + (size_t)v * NN * NH;
        float4 a = make_float4(0.f, 0.f, 0.f, 0.f);
#pragma unroll 4
        for (int j = beg; j < end; j++) {
            int2 m = cp[j];
            float nm = __int_as_float(m.y);
            uint2 raw = *(const uint2*)&xwp[(size_t)m.x * NH + q * 4];
            float2 f01 = __half22float2(*(__half2*)&raw.x);
            float2 f23 = __half22float2(*(__half2*)&raw.y);
            a.x += nm * f01.x; a.y += nm * f01.y;
            a.z += nm * f23.x; a.w += nm * f23.y;
        }
        // self loop
        float di = g_dinv1[v * NN + node];
        float sn = di * di;
        uint2 sr = *(const uint2*)&xwp[(size_t)node * NH + q * 4];
        float2 s01 = __half22float2(*(__half2*)&sr.x);
        float2 s23 = __half22float2(*(__half2*)&sr.y);
        float4 bv = *(const float4*)&b1[q * 4];
        float4 h;
        h.x = fmaxf(a.x + s01.x * sn + bv.x, 0.f);
        h.y = fmaxf(a.y + s01.y * sn + bv.y, 0.f);
        h.z = fmaxf(a.z + s23.x * sn + bv.z, 0.f);
        h.w = fmaxf(a.w + s23.y * sn + bv.w, 0.f);
        fo.x += h.x; fo.y += h.y; fo.z += h.z; fo.w += h.w;
        float4 w2 = *(const float4*)&W2[q * 4];
        dot[v] = h.x * w2.x + h.y * w2.y + h.z * w2.z + h.w * w2.w;
    }
#pragma unroll
    for (int o = 8; o > 0; o >>= 1) {
        dot[0] += __shfl_xor_sync(0xFFFFFFFFu, dot[0], o);
        dot[1] += __shfl_xor_sync(0xFFFFFFFFu, dot[1], o);
        dot[2] += __shfl_xor_sync(0xFFFFFFFFu, dot[2], o);
    }
    if (q == 0) {
#pragma unroll
        for (int v = 0; v < 3; v++)
            g_hws[v * NN + node] = dot[v] * g_dinv2[v * NN + node];
    }
    *(float4*)&out_feat[node * NH + q * 4] = fo;
}

// conv2 pull
__global__ void k_gather2(const float* __restrict__ b2a, const float* __restrict__ b2b, const float* __restrict__ b2c,
                          float* __restrict__ out) {
    int i = blockIdx.x * blockDim.x + threadIdx.x;
    if (i >= NN) return;
    float acc = 0.f;
#pragma unroll
    for (int v = 0; v < 3; v++) {
        const float* b2 = v == 0 ? b2a : v == 1 ? b2b : b2c;
        int beg = g_off[v * (NN + 1) + i];
        int end = g_off[v * (NN + 1) + i + 1];
        const int2* cp = g_csr + v * EMAX;
        float t = 0.f;
#pragma unroll 8
        for (int j = beg; j < end; j++)
            t += g_hws[v * NN + cp[j].x];
        float di = g_dinv2[v * NN + i];
        acc += di * t + g_hws[v * NN + i] * di + b2[0];
    }
    out[i] = acc;
}

extern "C" void kernel_launch(void* const* d_in, const int* in_sizes, int n_in,
                              void* d_out, int out_size) {
    const float* x = (const float*)d_in[0];
    const int* e0 = (const int*)d_in[1];
    const int* e1 = (const int*)d_in[2];
    const int* e2 = (const int*)d_in[3];
    const float* w0 = (const float*)d_in[4];
    const float* w1 = (const float*)d_in[5];
    const float* w2 = (const float*)d_in[6];
    const float* W1a = (const float*)d_in[7];
    const float* b1a = (const float*)d_in[8];
    const float* W2a = (const float*)d_in[9];
    const float* b2a = (const float*)d_in[10];
    const float* W1b = (const float*)d_in[11];
    const float* b1b = (const float*)d_in[12];
    const float* W2b = (const float*)d_in[13];
    const float* b2b = (const float*)d_in[14];
    const float* W1c = (const float*)d_in[15];
    const float* b1c = (const float*)d_in[16];
    const float* W2c = (const float*)d_in[17];
    const float* b2c = (const float*)d_in[18];
    float* out = (float*)d_out;
    int E = in_sizes[4];

    k_zero<<<(3 * NN * 2 + 255) / 256, 256>>>();

    dim3 gedge((E + 255) / 256, 3);
    k_deg<<<gedge, 256>>>(e0, e1, e2, w0, w1, w2, E);

    dim3 gscan(SCAN_B, 3);
    k_scanA<<<gscan, 256>>>();
    k_scanB<<<1, 96>>>();
    k_scanC<<<gscan, 256>>>(E);

    k_fill<<<gedge, 256>>>(e0, e1, e2, w0, w1, w2, E);

    dim3 ggemm((NN + 127) / 128, 3);
    k_gemm3<<<ggemm, 256>>>(x, W1a, W1b, W1c);

    k_gather1<<<(NN * 16 + 255) / 256, 256>>>(b1a, b1b, b1c, W2a, W2b, W2c, out + NN);

    k_gather2<<<(NN + 255) / 256, 256>>>(b2a, b2b, b2c, out);
}

// round 8
// speedup vs baseline: 3.2485x; 1.0443x over previous
#include <cuda_runtime.h>
#include <cuda_fp16.h>
#include <cstdint>

#define NN 50000
#define FIN 256
#define NH 64
#define EMAX 800000
#define SCAN_B 196            // blocks per view in hierarchical scan (196*256 >= 50000)

// Scratch (allocation-free rule: __device__ globals)
__device__ __half g_xwh[3 * NN * NH];   // x @ W1 per view (fp16 storage)
__device__ float g_degc[3 * NN * 2];    // interleaved {weighted deg, count} per node
__device__ int   g_off[3 * (NN + 1)];   // CSR offsets per view
__device__ int   g_cur[3 * NN];         // fill cursors
__device__ int2  g_csr[3 * EMAX];       // CSR: {src, float_bits(norm)} per in-edge
__device__ int   g_bsum[3 * SCAN_B];    // per-block count sums (scan level 1)
__device__ float g_dinv1[3 * NN];
__device__ float g_dinv2[3 * NN];
__device__ float g_hws[3 * NN];         // (h @ W2) * dinv2

__device__ __forceinline__ void red_v2(float* p, float a, float b) {
    asm volatile("red.global.add.v2.f32 [%0], {%1,%2};"
                 :: "l"(p), "f"(a), "f"(b) : "memory");
}
__device__ __forceinline__ uint32_t to_tf32(float f) {
    uint32_t r;
    asm("cvt.rna.tf32.f32 %0, %1;" : "=r"(r) : "f"(f));
    return r;
}

__global__ void k_zero() {
    int i = blockIdx.x * blockDim.x + threadIdx.x;
    if (i < 3 * NN * 2) g_degc[i] = 0.f;
}

// degree histogram: one vector red per edge
__global__ void k_deg(const int* __restrict__ e0, const int* __restrict__ e1, const int* __restrict__ e2,
                      const float* __restrict__ w0, const float* __restrict__ w1, const float* __restrict__ w2,
                      int E) {
    int e = blockIdx.x * blockDim.x + threadIdx.x;
    if (e >= E) return;
    int v = blockIdx.y;
    const int* ei = v == 0 ? e0 : v == 1 ? e1 : e2;
    const float* ew = v == 0 ? w0 : v == 1 ? w1 : w2;
    int d = ei[E + e];
    red_v2(&g_degc[(v * NN + d) * 2], ew[e], 1.f);
}

// scan level 1: per-block (256-node) count sums, coalesced
__global__ void k_scanA() {
    __shared__ int sm[8];
    int v = blockIdx.y;
    int idx = blockIdx.x * 256 + threadIdx.x;
    int c = (idx < NN) ? (int)g_degc[(v * NN + idx) * 2 + 1] : 0;
#pragma unroll
    for (int o = 16; o > 0; o >>= 1) c += __shfl_xor_sync(0xFFFFFFFFu, c, o);
    if ((threadIdx.x & 31) == 0) sm[threadIdx.x >> 5] = c;
    __syncthreads();
    if (threadIdx.x == 0) {
        int s = 0;
#pragma unroll
        for (int i = 0; i < 8; i++) s += sm[i];
        g_bsum[v * SCAN_B + blockIdx.x] = s;
    }
}

// scan level 2: exclusive scan of SCAN_B block sums per view; warp w handles view w
__global__ void k_scanB() {
    int w = threadIdx.x >> 5;
    int lane = threadIdx.x & 31;
    if (w >= 3) return;
    int run = 0;
    for (int base = 0; base < SCAN_B; base += 32) {
        int i = base + lane;
        int val = (i < SCAN_B) ? g_bsum[w * SCAN_B + i] : 0;
        int orig = val;
#pragma unroll
        for (int o = 1; o < 32; o <<= 1) {
            int y = __shfl_up_sync(0xFFFFFFFFu, val, o);
            if (lane >= o) val += y;
        }
        if (i < SCAN_B) g_bsum[w * SCAN_B + i] = run + val - orig;  // exclusive
        run += __shfl_sync(0xFFFFFFFFu, val, 31);
    }
}

// scan level 3: block-local exclusive scan + base; writes off, cur, dinv1, dinv2
__global__ void k_scanC(int E) {
    __shared__ int sm[256];
    int v = blockIdx.y;
    int idx = blockIdx.x * 256 + threadIdx.x;
    int t = threadIdx.x;
    float dw = 0.f;
    int c = 0;
    if (idx < NN) {
        dw = g_degc[(v * NN + idx) * 2 + 0];
        c  = (int)g_degc[(v * NN + idx) * 2 + 1];
    }
    sm[t] = c;
    __syncthreads();
    for (int o = 1; o < 256; o <<= 1) {
        int y = (t >= o) ? sm[t - o] : 0;
        __syncthreads();
        if (t >= o) sm[t] += y;
        __syncthreads();
    }
    if (idx < NN) {
        int base = g_bsum[v * SCAN_B + blockIdx.x];
        int off = base + sm[t] - c;    // exclusive
        g_off[v * (NN + 1) + idx] = off;
        g_cur[v * NN + idx] = off;
        g_dinv1[v * NN + idx] = rsqrtf(1.f + dw);
        g_dinv2[v * NN + idx] = rsqrtf(1.f + (float)c);
    }
    if (blockIdx.x == 0 && t == 0) g_off[v * (NN + 1) + NN] = E;
}

// CSR fill: packed {src, norm}
__global__ void k_fill(const int* __restrict__ e0, const int* __restrict__ e1, const int* __restrict__ e2,
                       const float* __restrict__ w0, const float* __restrict__ w1, const float* __restrict__ w2,
                       int E) {
    int e = blockIdx.x * blockDim.x + threadIdx.x;
    if (e >= E) return;
    int v = blockIdx.y;
    const int* ei = v == 0 ? e0 : v == 1 ? e1 : e2;
    const float* ew = v == 0 ? w0 : v == 1 ? w1 : w2;
    int s = ei[e];
    int d = ei[E + e];
    int pos = atomicAdd(&g_cur[v * NN + d], 1);
    float nrm = g_dinv1[v * NN + s] * ew[e] * g_dinv1[v * NN + d];
    g_csr[v * EMAX + pos] = make_int2(s, __float_as_int(nrm));
}

// xw = x @ W1 for all 3 views via tf32 mma.sync.m16n8k8; fp16 output.
__global__ void k_gemm3(const float* __restrict__ x,
                        const float* __restrict__ W1a, const float* __restrict__ W1b,
                        const float* __restrict__ W1c) {
    int v = blockIdx.y;
    const float* W = v == 0 ? W1a : v == 1 ? W1b : W1c;
    __shared__ uint32_t xs[128][36];   // [row][k] tf32
    __shared__ uint32_t ws[32][68];    // [k][col] tf32
    int tid  = threadIdx.x;
    int wid  = tid >> 5;
    int lane = tid & 31;
    int g = lane >> 2;
    int t = lane & 3;
    int row0 = blockIdx.x * 128;
    int wr = wid * 16;

    float c[8][4];
#pragma unroll
    for (int nt = 0; nt < 8; nt++)
#pragma unroll
        for (int i = 0; i < 4; i++) c[nt][i] = 0.f;

    for (int kc = 0; kc < FIN; kc += 32) {
#pragma unroll
        for (int j = 0; j < 4; j++) {
            int idx = tid + j * 256;
            int r = idx >> 3, f4 = idx & 7;
            int gr = row0 + r;
            float4 xv = make_float4(0.f, 0.f, 0.f, 0.f);
            if (gr < NN) xv = *(const float4*)&x[gr * FIN + kc + f4 * 4];
            uint32_t* p = &xs[r][f4 * 4];
            p[0] = to_tf32(xv.x); p[1] = to_tf32(xv.y);
            p[2] = to_tf32(xv.z); p[3] = to_tf32(xv.w);
        }
#pragma unroll
        for (int j = 0; j < 2; j++) {
            int idx = tid + j * 256;
            int kr = idx >> 4, c4 = idx & 15;
            float4 wv = *(const float4*)&W[(kc + kr) * NH + c4 * 4];
            uint32_t* p = &ws[kr][c4 * 4];
            p[0] = to_tf32(wv.x); p[1] = to_tf32(wv.y);
            p[2] = to_tf32(wv.z); p[3] = to_tf32(wv.w);
        }
        __syncthreads();
#pragma unroll
        for (int k0 = 0; k0 < 32; k0 += 8) {
            uint32_t a0 = xs[wr + g][k0 + t];
            uint32_t a1 = xs[wr + g + 8][k0 + t];
            uint32_t a2 = xs[wr + g][k0 + t + 4];
            uint32_t a3 = xs[wr + g + 8][k0 + t + 4];
#pragma unroll
            for (int nt = 0; nt < 8; nt++) {
                uint32_t b0 = ws[k0 + t][nt * 8 + g];
                uint32_t b1 = ws[k0 + t + 4][nt * 8 + g];
                asm volatile(
                    "mma.sync.aligned.m16n8k8.row.col.f32.tf32.tf32.f32 "
                    "{%0,%1,%2,%3}, {%4,%5,%6,%7}, {%8,%9}, {%0,%1,%2,%3};"
                    : "+f"(c[nt][0]), "+f"(c[nt][1]), "+f"(c[nt][2]), "+f"(c[nt][3])
                    : "r"(a0), "r"(a1), "r"(a2), "r"(a3), "r"(b0), "r"(b1));
            }
        }
        __syncthreads();
    }
    size_t vb = (size_t)v * NN * NH;
    int r0 = row0 + wr + g;
    int r1 = r0 + 8;
#pragma unroll
    for (int nt = 0; nt < 8; nt++) {
        int col = nt * 8 + t * 2;
        if (r0 < NN) *(__half2*)&g_xwh[vb + (size_t)r0 * NH + col] = __floats2half2_rn(c[nt][0], c[nt][1]);
        if (r1 < NN) *(__half2*)&g_xwh[vb + (size_t)r1 * NH + col] = __floats2half2_rn(c[nt][2], c[nt][3]);
    }
}

// conv1 pull + epilogue: 16 lanes per node, 4 features (fp16 loads) each.
__global__ void k_gather1(const float* __restrict__ b1a, const float* __restrict__ b1b, const float* __restrict__ b1c,
                          const float* __restrict__ W2a, const float* __restrict__ W2b, const float* __restrict__ W2c,
                          float* __restrict__ out_feat) {
    int gtid = blockIdx.x * blockDim.x + threadIdx.x;
    int node = gtid >> 4;
    if (node >= NN) return;
    int q = threadIdx.x & 15;

    float4 fo = make_float4(0.f, 0.f, 0.f, 0.f);
    float dot[3];
#pragma unroll
    for (int v = 0; v < 3; v++) {
        const float* b1 = v == 0 ? b1a : v == 1 ? b1b : b1c;
        const float* W2 = v == 0 ? W2a : v == 1 ? W2b : W2c;
        int beg = g_off[v * (NN + 1) + node];
        int end = g_off[v * (NN + 1) + node + 1];
        const int2* cp = g_csr + v * EMAX;
        const __half* xwp = g_xwh + (size_t)v * NN * NH;
        float4 a = make_float4(0.f, 0.f, 0.f, 0.f);
#pragma unroll 4
        for (int j = beg; j < end; j++) {
            int2 m = cp[j];
            float nm = __int_as_float(m.y);
            uint2 raw = *(const uint2*)&xwp[(size_t)m.x * NH + q * 4];
            float2 f01 = __half22float2(*(__half2*)&raw.x);
            float2 f23 = __half22float2(*(__half2*)&raw.y);
            a.x += nm * f01.x; a.y += nm * f01.y;
            a.z += nm * f23.x; a.w += nm * f23.y;
        }
        // self loop
        float di = g_dinv1[v * NN + node];
        float sn = di * di;
        uint2 sr = *(const uint2*)&xwp[(size_t)node * NH + q * 4];
        float2 s01 = __half22float2(*(__half2*)&sr.x);
        float2 s23 = __half22float2(*(__half2*)&sr.y);
        float4 bv = *(const float4*)&b1[q * 4];
        float4 h;
        h.x = fmaxf(a.x + s01.x * sn + bv.x, 0.f);
        h.y = fmaxf(a.y + s01.y * sn + bv.y, 0.f);
        h.z = fmaxf(a.z + s23.x * sn + bv.z, 0.f);
        h.w = fmaxf(a.w + s23.y * sn + bv.w, 0.f);
        fo.x += h.x; fo.y += h.y; fo.z += h.z; fo.w += h.w;
        float4 w2 = *(const float4*)&W2[q * 4];
        dot[v] = h.x * w2.x + h.y * w2.y + h.z * w2.z + h.w * w2.w;
    }
#pragma unroll
    for (int o = 8; o > 0; o >>= 1) {
        dot[0] += __shfl_xor_sync(0xFFFFFFFFu, dot[0], o);
        dot[1] += __shfl_xor_sync(0xFFFFFFFFu, dot[1], o);
        dot[2] += __shfl_xor_sync(0xFFFFFFFFu, dot[2], o);
    }
    if (q == 0) {
#pragma unroll
        for (int v = 0; v < 3; v++)
            g_hws[v * NN + node] = dot[v] * g_dinv2[v * NN + node];
    }
    *(float4*)&out_feat[node * NH + q * 4] = fo;
}

// conv2 pull
__global__ void k_gather2(const float* __restrict__ b2a, const float* __restrict__ b2b, const float* __restrict__ b2c,
                          float* __restrict__ out) {
    int i = blockIdx.x * blockDim.x + threadIdx.x;
    if (i >= NN) return;
    float acc = 0.f;
#pragma unroll
    for (int v = 0; v < 3; v++) {
        const float* b2 = v == 0 ? b2a : v == 1 ? b2b : b2c;
        int beg = g_off[v * (NN + 1) + i];
        int end = g_off[v * (NN + 1) + i + 1];
        const int2* cp = g_csr + v * EMAX;
        float t = 0.f;
#pragma unroll 8
        for (int j = beg; j < end; j++)
            t += g_hws[v * NN + cp[j].x];
        float di = g_dinv2[v * NN + i];
        acc += di * t + g_hws[v * NN + i] * di + b2[0];
    }
    out[i] = acc;
}

extern "C" void kernel_launch(void* const* d_in, const int* in_sizes, int n_in,
                              void* d_out, int out_size) {
    const float* x = (const float*)d_in[0];
    const int* e0 = (const int*)d_in[1];
    const int* e1 = (const int*)d_in[2];
    const int* e2 = (const int*)d_in[3];
    const float* w0 = (const float*)d_in[4];
    const float* w1 = (const float*)d_in[5];
    const float* w2 = (const float*)d_in[6];
    const float* W1a = (const float*)d_in[7];
    const float* b1a = (const float*)d_in[8];
    const float* W2a = (const float*)d_in[9];
    const float* b2a = (const float*)d_in[10];
    const float* W1b = (const float*)d_in[11];
    const float* b1b = (const float*)d_in[12];
    const float* W2b = (const float*)d_in[13];
    const float* b2b = (const float*)d_in[14];
    const float* W1c = (const float*)d_in[15];
    const float* b1c = (const float*)d_in[16];
    const float* W2c = (const float*)d_in[17];
    const float* b2c = (const float*)d_in[18];
    float* out = (float*)d_out;
    int E = in_sizes[4];

    // One-time stream/event setup (host-side only; no device memory).
    static cudaStream_t s2 = nullptr;
    static cudaEvent_t evFork = nullptr, evGemm = nullptr;
    if (s2 == nullptr) {
        cudaStreamCreateWithFlags(&s2, cudaStreamNonBlocking);
        cudaEventCreateWithFlags(&evFork, cudaEventDisableTiming);
        cudaEventCreateWithFlags(&evGemm, cudaEventDisableTiming);
    }

    // Fork: GEMM runs on s2 concurrently with the CSR-build chain on the legacy stream.
    cudaEventRecord(evFork, 0);
    cudaStreamWaitEvent(s2, evFork, 0);
    dim3 ggemm((NN + 127) / 128, 3);
    k_gemm3<<<ggemm, 256, 0, s2>>>(x, W1a, W1b, W1c);
    cudaEventRecord(evGemm, s2);

    // Edge pipeline on legacy stream
    k_zero<<<(3 * NN * 2 + 255) / 256, 256>>>();

    dim3 gedge((E + 255) / 256, 3);
    k_deg<<<gedge, 256>>>(e0, e1, e2, w0, w1, w2, E);

    dim3 gscan(SCAN_B, 3);
    k_scanA<<<gscan, 256>>>();
    k_scanB<<<1, 96>>>();
    k_scanC<<<gscan, 256>>>(E);

    k_fill<<<gedge, 256>>>(e0, e1, e2, w0, w1, w2, E);

    // Join: gather1 needs both the CSR and g_xwh
    cudaStreamWaitEvent(0, evGemm, 0);

    k_gather1<<<(NN * 16 + 255) / 256, 256>>>(b1a, b1b, b1c, W2a, W2b, W2c, out + NN);

    k_gather2<<<(NN + 255) / 256, 256>>>(b2a, b2b, b2c, out);
}

// round 9
// speedup vs baseline: 3.4848x; 1.0727x over previous
#include <cuda_runtime.h>
#include <cuda_fp16.h>
#include <cstdint>

#define NN 50000
#define FIN 256
#define NH 64
#define EMAX 800000
#define SCAN_B 196            // blocks per view in hierarchical scan (196*256 >= 50000)

// Scratch (allocation-free rule: __device__ globals)
__device__ __half g_xwh[3 * NN * NH];   // x @ W1 per view (fp16 storage)
__device__ float g_degc[3 * NN * 2];    // interleaved {weighted deg, count} per node (zeroed by scanC)
__device__ int   g_off[3 * (NN + 1)];   // CSR offsets per view
__device__ int   g_cur[3 * NN];         // fill cursors
__device__ int2  g_csr[3 * EMAX];       // CSR: {src, float_bits(norm)} per in-edge
__device__ int   g_bsum[3 * SCAN_B];    // per-block count sums (scan level 1)
__device__ float g_dinv1[3 * NN];
__device__ float g_dinv2[3 * NN];
__device__ float g_hws[3 * NN];         // (h @ W2) * dinv2

__device__ __forceinline__ void red_v2(float* p, float a, float b) {
    asm volatile("red.global.add.v2.f32 [%0], {%1,%2};"
                 :: "l"(p), "f"(a), "f"(b) : "memory");
}
__device__ __forceinline__ uint32_t to_tf32(float f) {
    uint32_t r;
    asm("cvt.rna.tf32.f32 %0, %1;" : "=r"(r) : "f"(f));
    return r;
}

// degree histogram: one vector red per edge (g_degc pre-zeroed: first run by
// static init, subsequent runs by k_scanC's cleanup store)
__global__ void k_deg(const int* __restrict__ e0, const int* __restrict__ e1, const int* __restrict__ e2,
                      const float* __restrict__ w0, const float* __restrict__ w1, const float* __restrict__ w2,
                      int E) {
    int e = blockIdx.x * blockDim.x + threadIdx.x;
    if (e >= E) return;
    int v = blockIdx.y;
    const int* ei = v == 0 ? e0 : v == 1 ? e1 : e2;
    const float* ew = v == 0 ? w0 : v == 1 ? w1 : w2;
    int d = ei[E + e];
    red_v2(&g_degc[(v * NN + d) * 2], ew[e], 1.f);
}

// scan level 1: per-block (256-node) count sums, coalesced
__global__ void k_scanA() {
    __shared__ int sm[8];
    int v = blockIdx.y;
    int idx = blockIdx.x * 256 + threadIdx.x;
    int c = (idx < NN) ? (int)g_degc[(v * NN + idx) * 2 + 1] : 0;
#pragma unroll
    for (int o = 16; o > 0; o >>= 1) c += __shfl_xor_sync(0xFFFFFFFFu, c, o);
    if ((threadIdx.x & 31) == 0) sm[threadIdx.x >> 5] = c;
    __syncthreads();
    if (threadIdx.x == 0) {
        int s = 0;
#pragma unroll
        for (int i = 0; i < 8; i++) s += sm[i];
        g_bsum[v * SCAN_B + blockIdx.x] = s;
    }
}

// scan level 2: each block computes its own base (reduce of preceding block sums),
// block-local exclusive scan; writes off, cur, dinv1, dinv2; re-zeroes g_degc.
__global__ void k_scanC(int E) {
    __shared__ int sm[256];
    __shared__ int swarp[8];
    __shared__ int sbase;
    int v = blockIdx.y;
    int idx = blockIdx.x * 256 + threadIdx.x;
    int t = threadIdx.x;

    // base = sum of g_bsum[v][0 .. blockIdx.x)
    int bv = (t < blockIdx.x && t < SCAN_B) ? g_bsum[v * SCAN_B + t] : 0;
#pragma unroll
    for (int o = 16; o > 0; o >>= 1) bv += __shfl_xor_sync(0xFFFFFFFFu, bv, o);
    if ((t & 31) == 0) swarp[t >> 5] = bv;
    __syncthreads();
    if (t == 0) {
        int s = 0;
#pragma unroll
        for (int i = 0; i < 8; i++) s += swarp[i];
        sbase = s;
    }

    float dw = 0.f;
    int c = 0;
    if (idx < NN) {
        dw = g_degc[(v * NN + idx) * 2 + 0];
        c  = (int)g_degc[(v * NN + idx) * 2 + 1];
        // cleanup for next replay
        g_degc[(v * NN + idx) * 2 + 0] = 0.f;
        g_degc[(v * NN + idx) * 2 + 1] = 0.f;
    }
    sm[t] = c;
    __syncthreads();
    for (int o = 1; o < 256; o <<= 1) {
        int y = (t >= o) ? sm[t - o] : 0;
        __syncthreads();
        if (t >= o) sm[t] += y;
        __syncthreads();
    }
    if (idx < NN) {
        int off = sbase + sm[t] - c;    // exclusive
        g_off[v * (NN + 1) + idx] = off;
        g_cur[v * NN + idx] = off;
        g_dinv1[v * NN + idx] = rsqrtf(1.f + dw);
        g_dinv2[v * NN + idx] = rsqrtf(1.f + (float)c);
    }
    if (blockIdx.x == 0 && t == 0) g_off[v * (NN + 1) + NN] = E;
}

// CSR fill: packed {src, norm}
__global__ void k_fill(const int* __restrict__ e0, const int* __restrict__ e1, const int* __restrict__ e2,
                       const float* __restrict__ w0, const float* __restrict__ w1, const float* __restrict__ w2,
                       int E) {
    int e = blockIdx.x * blockDim.x + threadIdx.x;
    if (e >= E) return;
    int v = blockIdx.y;
    const int* ei = v == 0 ? e0 : v == 1 ? e1 : e2;
    const float* ew = v == 0 ? w0 : v == 1 ? w1 : w2;
    int s = ei[e];
    int d = ei[E + e];
    int pos = atomicAdd(&g_cur[v * NN + d], 1);
    float nrm = g_dinv1[v * NN + s] * ew[e] * g_dinv1[v * NN + d];
    g_csr[v * EMAX + pos] = make_int2(s, __float_as_int(nrm));
}

// xw = x @ W1 for all 3 views via tf32 mma.sync.m16n8k8; fp16 output.
__global__ void k_gemm3(const float* __restrict__ x,
                        const float* __restrict__ W1a, const float* __restrict__ W1b,
                        const float* __restrict__ W1c) {
    int v = blockIdx.y;
    const float* W = v == 0 ? W1a : v == 1 ? W1b : W1c;
    __shared__ uint32_t xs[128][36];   // [row][k] tf32
    __shared__ uint32_t ws[32][68];    // [k][col] tf32
    int tid  = threadIdx.x;
    int wid  = tid >> 5;
    int lane = tid & 31;
    int g = lane >> 2;
    int t = lane & 3;
    int row0 = blockIdx.x * 128;
    int wr = wid * 16;

    float c[8][4];
#pragma unroll
    for (int nt = 0; nt < 8; nt++)
#pragma unroll
        for (int i = 0; i < 4; i++) c[nt][i] = 0.f;

    for (int kc = 0; kc < FIN; kc += 32) {
#pragma unroll
        for (int j = 0; j < 4; j++) {
            int idx = tid + j * 256;
            int r = idx >> 3, f4 = idx & 7;
            int gr = row0 + r;
            float4 xv = make_float4(0.f, 0.f, 0.f, 0.f);
            if (gr < NN) xv = *(const float4*)&x[gr * FIN + kc + f4 * 4];
            uint32_t* p = &xs[r][f4 * 4];
            p[0] = to_tf32(xv.x); p[1] = to_tf32(xv.y);
            p[2] = to_tf32(xv.z); p[3] = to_tf32(xv.w);
        }
#pragma unroll
        for (int j = 0; j < 2; j++) {
            int idx = tid + j * 256;
            int kr = idx >> 4, c4 = idx & 15;
            float4 wv = *(const float4*)&W[(kc + kr) * NH + c4 * 4];
            uint32_t* p = &ws[kr][c4 * 4];
            p[0] = to_tf32(wv.x); p[1] = to_tf32(wv.y);
            p[2] = to_tf32(wv.z); p[3] = to_tf32(wv.w);
        }
        __syncthreads();
#pragma unroll
        for (int k0 = 0; k0 < 32; k0 += 8) {
            uint32_t a0 = xs[wr + g][k0 + t];
            uint32_t a1 = xs[wr + g + 8][k0 + t];
            uint32_t a2 = xs[wr + g][k0 + t + 4];
            uint32_t a3 = xs[wr + g + 8][k0 + t + 4];
#pragma unroll
            for (int nt = 0; nt < 8; nt++) {
                uint32_t b0 = ws[k0 + t][nt * 8 + g];
                uint32_t b1 = ws[k0 + t + 4][nt * 8 + g];
                asm volatile(
                    "mma.sync.aligned.m16n8k8.row.col.f32.tf32.tf32.f32 "
                    "{%0,%1,%2,%3}, {%4,%5,%6,%7}, {%8,%9}, {%0,%1,%2,%3};"
                    : "+f"(c[nt][0]), "+f"(c[nt][1]), "+f"(c[nt][2]), "+f"(c[nt][3])
                    : "r"(a0), "r"(a1), "r"(a2), "r"(a3), "r"(b0), "r"(b1));
            }
        }
        __syncthreads();
    }
    size_t vb = (size_t)v * NN * NH;
    int r0 = row0 + wr + g;
    int r1 = r0 + 8;
#pragma unroll
    for (int nt = 0; nt < 8; nt++) {
        int col = nt * 8 + t * 2;
        if (r0 < NN) *(__half2*)&g_xwh[vb + (size_t)r0 * NH + col] = __floats2half2_rn(c[nt][0], c[nt][1]);
        if (r1 < NN) *(__half2*)&g_xwh[vb + (size_t)r1 * NH + col] = __floats2half2_rn(c[nt][2], c[nt][3]);
    }
}

// conv1 pull + epilogue: 8 lanes per node, 8 fp16 features (one uint4) each.
__global__ void k_gather1(const float* __restrict__ b1a, const float* __restrict__ b1b, const float* __restrict__ b1c,
                          const float* __restrict__ W2a, const float* __restrict__ W2b, const float* __restrict__ W2c,
                          float* __restrict__ out_feat) {
    int gtid = blockIdx.x * blockDim.x + threadIdx.x;
    int node = gtid >> 3;
    if (node >= NN) return;
    int q = threadIdx.x & 7;        // 8B-half chunk: features q*8 .. q*8+7

    float fo[8];
#pragma unroll
    for (int i = 0; i < 8; i++) fo[i] = 0.f;
    float dot[3];
#pragma unroll
    for (int v = 0; v < 3; v++) {
        const float* b1 = v == 0 ? b1a : v == 1 ? b1b : b1c;
        const float* W2 = v == 0 ? W2a : v == 1 ? W2b : W2c;
        int beg = g_off[v * (NN + 1) + node];
        int end = g_off[v * (NN + 1) + node + 1];
        const int2* cp = g_csr + v * EMAX;
        const uint4* xw8 = (const uint4*)(g_xwh + (size_t)v * NN * NH);
        float a[8];
#pragma unroll
        for (int i = 0; i < 8; i++) a[i] = 0.f;
#pragma unroll 4
        for (int j = beg; j < end; j++) {
            int2 m = cp[j];
            float nm = __int_as_float(m.y);
            uint4 raw = xw8[(size_t)m.x * 8 + q];
            float2 f0 = __half22float2(*(__half2*)&raw.x);
            float2 f1 = __half22float2(*(__half2*)&raw.y);
            float2 f2 = __half22float2(*(__half2*)&raw.z);
            float2 f3 = __half22float2(*(__half2*)&raw.w);
            a[0] += nm * f0.x; a[1] += nm * f0.y;
            a[2] += nm * f1.x; a[3] += nm * f1.y;
            a[4] += nm * f2.x; a[5] += nm * f2.y;
            a[6] += nm * f3.x; a[7] += nm * f3.y;
        }
        // self loop
        float di = g_dinv1[v * NN + node];
        float sn = di * di;
        uint4 sr = xw8[(size_t)node * 8 + q];
        float2 s0 = __half22float2(*(__half2*)&sr.x);
        float2 s1 = __half22float2(*(__half2*)&sr.y);
        float2 s2 = __half22float2(*(__half2*)&sr.z);
        float2 s3 = __half22float2(*(__half2*)&sr.w);
        float sf[8] = {s0.x, s0.y, s1.x, s1.y, s2.x, s2.y, s3.x, s3.y};
        float4 bva = *(const float4*)&b1[q * 8];
        float4 bvb = *(const float4*)&b1[q * 8 + 4];
        float bv[8] = {bva.x, bva.y, bva.z, bva.w, bvb.x, bvb.y, bvb.z, bvb.w};
        float4 w2a = *(const float4*)&W2[q * 8];
        float4 w2b = *(const float4*)&W2[q * 8 + 4];
        float w2[8] = {w2a.x, w2a.y, w2a.z, w2a.w, w2b.x, w2b.y, w2b.z, w2b.w};
        float dt = 0.f;
#pragma unroll
        for (int i = 0; i < 8; i++) {
            float hv = fmaxf(a[i] + sf[i] * sn + bv[i], 0.f);
            fo[i] += hv;
            dt += hv * w2[i];
        }
        dot[v] = dt;
    }
#pragma unroll
    for (int o = 4; o > 0; o >>= 1) {
        dot[0] += __shfl_xor_sync(0xFFFFFFFFu, dot[0], o);
        dot[1] += __shfl_xor_sync(0xFFFFFFFFu, dot[1], o);
        dot[2] += __shfl_xor_sync(0xFFFFFFFFu, dot[2], o);
    }
    if (q == 0) {
#pragma unroll
        for (int v = 0; v < 3; v++)
            g_hws[v * NN + node] = dot[v] * g_dinv2[v * NN + node];
    }
    *(float4*)&out_feat[node * NH + q * 8]     = make_float4(fo[0], fo[1], fo[2], fo[3]);
    *(float4*)&out_feat[node * NH + q * 8 + 4] = make_float4(fo[4], fo[5], fo[6], fo[7]);
}

// conv2 pull
__global__ void k_gather2(const float* __restrict__ b2a, const float* __restrict__ b2b, const float* __restrict__ b2c,
                          float* __restrict__ out) {
    int i = blockIdx.x * blockDim.x + threadIdx.x;
    if (i >= NN) return;
    float acc = 0.f;
#pragma unroll
    for (int v = 0; v < 3; v++) {
        const float* b2 = v == 0 ? b2a : v == 1 ? b2b : b2c;
        int beg = g_off[v * (NN + 1) + i];
        int end = g_off[v * (NN + 1) + i + 1];
        const int2* cp = g_csr + v * EMAX;
        float t = 0.f;
#pragma unroll 8
        for (int j = beg; j < end; j++)
            t += g_hws[v * NN + cp[j].x];
        float di = g_dinv2[v * NN + i];
        acc += di * t + g_hws[v * NN + i] * di + b2[0];
    }
    out[i] = acc;
}

extern "C" void kernel_launch(void* const* d_in, const int* in_sizes, int n_in,
                              void* d_out, int out_size) {
    const float* x = (const float*)d_in[0];
    const int* e0 = (const int*)d_in[1];
    const int* e1 = (const int*)d_in[2];
    const int* e2 = (const int*)d_in[3];
    const float* w0 = (const float*)d_in[4];
    const float* w1 = (const float*)d_in[5];
    const float* w2 = (const float*)d_in[6];
    const float* W1a = (const float*)d_in[7];
    const float* b1a = (const float*)d_in[8];
    const float* W2a = (const float*)d_in[9];
    const float* b2a = (const float*)d_in[10];
    const float* W1b = (const float*)d_in[11];
    const float* b1b = (const float*)d_in[12];
    const float* W2b = (const float*)d_in[13];
    const float* b2b = (const float*)d_in[14];
    const float* W1c = (const float*)d_in[15];
    const float* b1c = (const float*)d_in[16];
    const float* W2c = (const float*)d_in[17];
    const float* b2c = (const float*)d_in[18];
    float* out = (float*)d_out;
    int E = in_sizes[4];

    // One-time stream/event setup (host-side only; no device memory).
    static cudaStream_t s2 = nullptr;
    static cudaEvent_t evFork = nullptr, evGemm = nullptr;
    if (s2 == nullptr) {
        cudaStreamCreateWithFlags(&s2, cudaStreamNonBlocking);
        cudaEventCreateWithFlags(&evFork, cudaEventDisableTiming);
        cudaEventCreateWithFlags(&evGemm, cudaEventDisableTiming);
    }

    // Fork: GEMM runs on s2 concurrently with the CSR-build chain on the legacy stream.
    cudaEventRecord(evFork, 0);
    cudaStreamWaitEvent(s2, evFork, 0);
    dim3 ggemm((NN + 127) / 128, 3);
    k_gemm3<<<ggemm, 256, 0, s2>>>(x, W1a, W1b, W1c);
    cudaEventRecord(evGemm, s2);

    // Edge pipeline on legacy stream (g_degc zeroed by previous scanC / static init)
    dim3 gedge((E + 255) / 256, 3);
    k_deg<<<gedge, 256>>>(e0, e1, e2, w0, w1, w2, E);

    dim3 gscan(SCAN_B, 3);
    k_scanA<<<gscan, 256>>>();
    k_scanC<<<gscan, 256>>>(E);

    k_fill<<<gedge, 256>>>(e0, e1, e2, w0, w1, w2, E);

    // Join: gather1 needs both the CSR and g_xwh
    cudaStreamWaitEvent(0, evGemm, 0);

    k_gather1<<<(NN * 8 + 255) / 256, 256>>>(b1a, b1b, b1c, W2a, W2b, W2c, out + NN);

    k_gather2<<<(NN + 255) / 256, 256>>>(b2a, b2b, b2c, out);
}